// round 2
// baseline (speedup 1.0000x reference)
#include <cuda_runtime.h>
#include <math.h>

#define NN 10000
#define NE 160000

// ---------------- device scratch (no allocations allowed) ----------------
__device__ int   g_deg[NN];
__device__ int   g_off[NN + 1];
__device__ int   g_cur[NN];
__device__ int   g_ej[NE];
__device__ float g_env[NE];
__device__ float g_ux[NE];
__device__ float g_uy[NE];
__device__ float g_uz[NE];
__device__ float g_rbf[NE * 20];
__device__ float g_h[NN * 128];
__device__ float g_phi[NN * 384];
__device__ float g_va[NN * 384];   // SoA: [node][coord][128]
__device__ float g_vb[NN * 384];   // SoA

// ---------------- pass A: histogram of active-edge destinations -----------
__global__ void passA_kernel(const float* __restrict__ xyz,
                             const int* __restrict__ nbr) {
    int e = blockIdx.x * blockDim.x + threadIdx.x;
    if (e >= NE) return;
    int ni = nbr[2 * e], nj = nbr[2 * e + 1];
    float rx = xyz[3 * nj]     - xyz[3 * ni];
    float ry = xyz[3 * nj + 1] - xyz[3 * ni + 1];
    float rz = xyz[3 * nj + 2] - xyz[3 * ni + 2];
    float dist = sqrtf(rx * rx + ry * ry + rz * rz + 3e-15f);
    if (dist < 5.0f) atomicAdd(&g_deg[ni], 1);
}

// ---------------- exclusive scan over degrees (single block) --------------
__global__ void scan_kernel() {
    __shared__ int sdata[1024];
    __shared__ int carry_s;
    int t = threadIdx.x;
    if (t == 0) carry_s = 0;
    __syncthreads();
    for (int base = 0; base <= NN; base += 1024) {
        int idx = base + t;
        int v = (idx < NN) ? g_deg[idx] : 0;
        sdata[t] = v;
        __syncthreads();
        #pragma unroll
        for (int off = 1; off < 1024; off <<= 1) {
            int y = (t >= off) ? sdata[t - off] : 0;
            __syncthreads();
            sdata[t] += y;
            __syncthreads();
        }
        int c = carry_s;
        if (idx <= NN) {
            int excl = c + sdata[t] - v;
            g_off[idx] = excl;
            if (idx < NN) g_cur[idx] = excl;
        }
        __syncthreads();
        if (t == 0) carry_s = c + sdata[1023];
        __syncthreads();
    }
}

// ---------------- pass B: place edge data sorted by destination -----------
__global__ void passB_kernel(const float* __restrict__ xyz,
                             const int* __restrict__ nbr) {
    int e = blockIdx.x * blockDim.x + threadIdx.x;
    if (e >= NE) return;
    int ni = nbr[2 * e], nj = nbr[2 * e + 1];
    float rx = xyz[3 * nj]     - xyz[3 * ni];
    float ry = xyz[3 * nj + 1] - xyz[3 * ni + 1];
    float rz = xyz[3 * nj + 2] - xyz[3 * ni + 2];
    float dist = sqrtf(rx * rx + ry * ry + rz * rz + 3e-15f);
    if (dist >= 5.0f) return;
    int pos = atomicAdd(&g_cur[ni], 1);
    float inv = 1.0f / dist;
    g_ej[pos] = nj;
    g_ux[pos] = rx * inv;
    g_uy[pos] = ry * inv;
    g_uz[pos] = rz * inv;
    g_env[pos] = 0.5f * (cosf(dist * 0.6283185307179586f) + 1.0f);

    // rbf[k] = exp(-beta*(exp(-d)-mu_k)^2), mu_k linspace -> mult. recurrence
    const float MU0   = 0.006737946999085467f;   // exp(-5)
    const float DELTA = 0.05227695015794287f;    // (1-exp(-5))/19
    const float BETA  = 101.3613328f;            // (0.1*(1-exp(-5)))^-2
    float x  = expf(-dist);
    float u  = x - MU0;
    float a0 = expf(-BETA * u * u);
    float tt = expf(2.0f * BETA * DELTA * u);
    float s1 = expf(-BETA * DELTA * DELTA);
    float s2 = s1 * s1;
    float val = a0;
    float f = tt * s1;
    #pragma unroll
    for (int k = 0; k < 20; k++) {
        g_rbf[20 * pos + k] = val;
        val *= f;
        f *= s2;
    }
}

// ---------------- fp32 SGEMM 64x128 tiles, K=128: C = act(A@B + bias) -----
template<int ACT>
__global__ void __launch_bounds__(256)
gemm64(const float* __restrict__ A, const float* __restrict__ B,
       const float* __restrict__ bias, float* __restrict__ C,
       int M, int N) {
    __shared__ float As[32][68];
    __shared__ float Bs[32][132];
    int tid = threadIdx.x;
    int tx = tid & 15, ty = tid >> 4;
    int brow = blockIdx.x * 64;
    int bcol = blockIdx.y * 128;
    float acc[4][8];
    #pragma unroll
    for (int i = 0; i < 4; i++)
        #pragma unroll
        for (int j = 0; j < 8; j++) acc[i][j] = 0.f;

    for (int kt = 0; kt < 4; kt++) {
        #pragma unroll
        for (int r = 0; r < 8; r++) {
            int lin = tid + 256 * r;
            int m = lin >> 5, k = lin & 31;
            int gm = brow + m;
            As[k][m] = (gm < M) ? A[gm * 128 + kt * 32 + k] : 0.f;
        }
        #pragma unroll
        for (int r = 0; r < 16; r++) {
            int lin = tid + 256 * r;
            int k = lin >> 7, n = lin & 127;
            Bs[k][n] = B[(kt * 32 + k) * N + bcol + n];
        }
        __syncthreads();
        #pragma unroll
        for (int k = 0; k < 32; k++) {
            float4 a  = *reinterpret_cast<const float4*>(&As[k][ty * 4]);
            float4 b0 = *reinterpret_cast<const float4*>(&Bs[k][tx * 8]);
            float4 b1 = *reinterpret_cast<const float4*>(&Bs[k][tx * 8 + 4]);
            float av[4] = {a.x, a.y, a.z, a.w};
            float bv[8] = {b0.x, b0.y, b0.z, b0.w, b1.x, b1.y, b1.z, b1.w};
            #pragma unroll
            for (int i = 0; i < 4; i++)
                #pragma unroll
                for (int j = 0; j < 8; j++)
                    acc[i][j] += av[i] * bv[j];
        }
        __syncthreads();
    }
    float bv[8];
    #pragma unroll
    for (int j = 0; j < 8; j++) bv[j] = bias[bcol + tx * 8 + j];
    #pragma unroll
    for (int i = 0; i < 4; i++) {
        int row = brow + ty * 4 + i;
        if (row < M) {
            float o[8];
            #pragma unroll
            for (int j = 0; j < 8; j++) {
                float c = acc[i][j] + bv[j];
                if (ACT) c = c / (1.0f + expf(-c));   // silu
                o[j] = c;
            }
            float4* dst = reinterpret_cast<float4*>(&C[row * N + bcol + tx * 8]);
            dst[0] = make_float4(o[0], o[1], o[2], o[3]);
            dst[1] = make_float4(o[4], o[5], o[6], o[7]);
        }
    }
}

// ---------------- node-centric gather kernel (no atomics) ------------------
// v_in / v_out internal layout SoA: [node][coord][128]; final layer writes
// interleaved (node,128,3) into d_out.
template<bool FIRST, bool LAST>
__global__ void __launch_bounds__(128)
node_kernel(const float* __restrict__ phi, const float* __restrict__ v_in,
            float* __restrict__ s_io, float* __restrict__ v_out,
            const float* __restrict__ Wr, const float* __restrict__ brv) {
    int t = threadIdx.x;
    // Wr columns for features {t, 128+t, 256+t} in registers
    float wr[60];
    #pragma unroll
    for (int k = 0; k < 20; k++) {
        wr[k]      = Wr[k * 384 + t];
        wr[20 + k] = Wr[k * 384 + 128 + t];
        wr[40 + k] = Wr[k * 384 + 256 + t];
    }
    float br0 = brv[t], br1 = brv[128 + t], br2 = brv[256 + t];

    for (int i = blockIdx.x; i < NN; i += gridDim.x) {
        int beg = g_off[i], end = g_off[i + 1];
        float accs = 0.f, avx = 0.f, avy = 0.f, avz = 0.f;
        for (int e = beg; e < end; e++) {
            int j = __ldg(&g_ej[e]);
            float env = __ldg(&g_env[e]);
            float ux = __ldg(&g_ux[e]), uy = __ldg(&g_uy[e]), uz = __ldg(&g_uz[e]);
            const float4* rb = reinterpret_cast<const float4*>(g_rbf + e * 20);
            float4 r0 = __ldg(rb), r1 = __ldg(rb + 1), r2 = __ldg(rb + 2),
                   r3 = __ldg(rb + 3), r4 = __ldg(rb + 4);
            float rv[20] = {r0.x, r0.y, r0.z, r0.w, r1.x, r1.y, r1.z, r1.w,
                            r2.x, r2.y, r2.z, r2.w, r3.x, r3.y, r3.z, r3.w,
                            r4.x, r4.y, r4.z, r4.w};
            float ws0 = br0, ws1 = br1, ws2 = br2;
            #pragma unroll
            for (int k = 0; k < 20; k++) {
                ws0 += rv[k] * wr[k];
                ws1 += rv[k] * wr[20 + k];
                ws2 += rv[k] * wr[40 + k];
            }
            ws0 *= env; ws1 *= env; ws2 *= env;
            const float* pj = phi + (size_t)j * 384;
            float ds = pj[t] * ws0;
            float gv = pj[128 + t] * ws1;
            float gu = pj[256 + t] * ws2;
            accs += ds;
            if (FIRST) {
                avx += gu * ux; avy += gu * uy; avz += gu * uz;
            } else {
                const float* vj = v_in + (size_t)j * 384;
                avx += gu * ux + gv * vj[t];
                avy += gu * uy + gv * vj[128 + t];
                avz += gu * uz + gv * vj[256 + t];
            }
        }
        s_io[i * 128 + t] += accs;
        if (LAST) {
            const float* vi = v_in + (size_t)i * 384;
            v_out[i * 384 + 3 * t]     = vi[t]       + avx;
            v_out[i * 384 + 3 * t + 1] = vi[128 + t] + avy;
            v_out[i * 384 + 3 * t + 2] = vi[256 + t] + avz;
        } else if (FIRST) {
            v_out[i * 384 + t]       = avx;
            v_out[i * 384 + 128 + t] = avy;
            v_out[i * 384 + 256 + t] = avz;
        } else {
            const float* vi = v_in + (size_t)i * 384;
            v_out[i * 384 + t]       = vi[t]       + avx;
            v_out[i * 384 + 128 + t] = vi[128 + t] + avy;
            v_out[i * 384 + 256 + t] = vi[256 + t] + avz;
        }
    }
}

// ---------------- orchestration -------------------------------------------
extern "C" void kernel_launch(void* const* d_in, const int* in_sizes, int n_in,
                              void* d_out, int out_size) {
    (void)in_sizes; (void)n_in; (void)out_size;
    const float* xyz  = (const float*)d_in[0];
    const int*   nbr  = (const int*)d_in[1];
    const float* cg_s = (const float*)d_in[2];
    const float* W1   = (const float*)d_in[3];
    const float* b1   = (const float*)d_in[4];
    const float* W2   = (const float*)d_in[5];
    const float* b2   = (const float*)d_in[6];
    const float* Wr   = (const float*)d_in[7];
    const float* brr  = (const float*)d_in[8];
    float* s_out = (float*)d_out;                       // (N,128)
    float* v_out_final = s_out + (size_t)NN * 128;      // (N,128,3)

    void *p_deg, *p_h, *p_phi, *p_va, *p_vb;
    cudaGetSymbolAddress(&p_deg, g_deg);
    cudaGetSymbolAddress(&p_h, g_h);
    cudaGetSymbolAddress(&p_phi, g_phi);
    cudaGetSymbolAddress(&p_va, g_va);
    cudaGetSymbolAddress(&p_vb, g_vb);

    cudaMemsetAsync(p_deg, 0, NN * sizeof(int));
    cudaMemcpyAsync(s_out, cg_s, (size_t)NN * 128 * sizeof(float),
                    cudaMemcpyDeviceToDevice);

    passA_kernel<<<(NE + 255) / 256, 256>>>(xyz, nbr);
    scan_kernel<<<1, 1024>>>();
    passB_kernel<<<(NE + 255) / 256, 256>>>(xyz, nbr);

    dim3 g1((NN + 63) / 64, 1), g2((NN + 63) / 64, 3);

    // layer 0
    gemm64<1><<<g1, 256>>>(s_out, W1, b1, (float*)p_h, NN, 128);
    gemm64<0><<<g2, 256>>>((const float*)p_h, W2, b2, (float*)p_phi, NN, 384);
    node_kernel<true, false><<<1480, 128>>>((const float*)p_phi, nullptr,
                                            s_out, (float*)p_va, Wr, brr);
    // layer 1
    gemm64<1><<<g1, 256>>>(s_out, W1 + 128 * 128, b1 + 128, (float*)p_h, NN, 128);
    gemm64<0><<<g2, 256>>>((const float*)p_h, W2 + 128 * 384, b2 + 384,
                           (float*)p_phi, NN, 384);
    node_kernel<false, false><<<1480, 128>>>((const float*)p_phi, (const float*)p_va,
                                             s_out, (float*)p_vb,
                                             Wr + 20 * 384, brr + 384);
    // layer 2 (writes interleaved v into d_out)
    gemm64<1><<<g1, 256>>>(s_out, W1 + 2 * 128 * 128, b1 + 2 * 128, (float*)p_h, NN, 128);
    gemm64<0><<<g2, 256>>>((const float*)p_h, W2 + 2 * 128 * 384, b2 + 2 * 384,
                           (float*)p_phi, NN, 384);
    node_kernel<false, true><<<1480, 128>>>((const float*)p_phi, (const float*)p_vb,
                                            s_out, v_out_final,
                                            Wr + 2 * 20 * 384, brr + 2 * 384);
}

// round 3
// speedup vs baseline: 1.6009x; 1.6009x over previous
#include <cuda_runtime.h>
#include <math.h>

#define NN 10000
#define NE 160000

// ---------------- device scratch (no allocations allowed) ----------------
__device__ int   g_count;
__device__ int   g_ei[NE];
__device__ int   g_ej[NE];
__device__ float g_env[NE];
__device__ float g_ux[NE];
__device__ float g_uy[NE];
__device__ float g_uz[NE];
__device__ float g_rbf[NE * 20];
__device__ float g_h[NN * 128];
__device__ float g_phi[NN * 384];
__device__ float g_va[NN * 384];   // SoA: [node][coord][128]
__device__ float g_vb[NN * 384];   // SoA

__device__ __forceinline__ void red4(float* a, float x, float y, float z, float w) {
    asm volatile("red.global.add.v4.f32 [%0], {%1,%2,%3,%4};"
                 :: "l"(a), "f"(x), "f"(y), "f"(z), "f"(w) : "memory");
}

// ---------------- per-edge geometry + RBF precompute (with compaction) ----
__global__ void precompute_kernel(const float* __restrict__ xyz,
                                  const int* __restrict__ nbr) {
    int e = blockIdx.x * blockDim.x + threadIdx.x;
    bool active = false;
    int ni = 0, nj = 0;
    float rx = 0.f, ry = 0.f, rz = 0.f, dist = 1.f;
    if (e < NE) {
        ni = nbr[2 * e]; nj = nbr[2 * e + 1];
        float x0 = xyz[3 * ni], x1 = xyz[3 * ni + 1], x2 = xyz[3 * ni + 2];
        rx = xyz[3 * nj]     - x0;
        ry = xyz[3 * nj + 1] - x1;
        rz = xyz[3 * nj + 2] - x2;
        dist = sqrtf(rx * rx + ry * ry + rz * rz + 3e-15f);
        active = (dist < 5.0f);   // env==0 edges contribute nothing: drop them
    }
    unsigned mask = __ballot_sync(0xffffffffu, active);
    if (!active) return;
    int lane = threadIdx.x & 31;
    int rank = __popc(mask & ((1u << lane) - 1u));
    int leader = __ffs((int)mask) - 1;
    int base = 0;
    if (lane == leader) base = atomicAdd(&g_count, __popc(mask));
    base = __shfl_sync(mask, base, leader);
    int pos = base + rank;

    float inv = 1.0f / dist;
    g_ei[pos] = ni; g_ej[pos] = nj;
    g_ux[pos] = rx * inv;
    g_uy[pos] = ry * inv;
    g_uz[pos] = rz * inv;
    g_env[pos] = 0.5f * (cosf(dist * 0.6283185307179586f) + 1.0f);

    // rbf[k] = exp(-beta*(exp(-d)-mu_k)^2), mu_k linspace -> mult. recurrence
    const float MU0   = 0.006737946999085467f;   // exp(-5)
    const float DELTA = 0.05227695015794287f;    // (1-exp(-5))/19
    const float BETA  = 101.3613328f;            // (0.1*(1-exp(-5)))^-2
    float x  = expf(-dist);
    float u  = x - MU0;
    float a0 = expf(-BETA * u * u);
    float tt = expf(2.0f * BETA * DELTA * u);
    float s1 = expf(-BETA * DELTA * DELTA);
    float s2 = s1 * s1;
    float val = a0;
    float f = tt * s1;
    #pragma unroll
    for (int k = 0; k < 20; k++) {
        g_rbf[20 * pos + k] = val;
        val *= f;
        f *= s2;
    }
}

// ---------------- fp32 SGEMM 64x64 tiles, K=128: C = act(A@B + bias) ------
template<int ACT>
__global__ void __launch_bounds__(128)
gemm64x64(const float* __restrict__ A, const float* __restrict__ B,
          const float* __restrict__ bias, float* __restrict__ C,
          int M, int N) {
    __shared__ float As[32][68];
    __shared__ float Bs[32][68];
    int tid = threadIdx.x;
    int tx = tid & 15, ty = tid >> 4;       // tx: 16 col-groups(4), ty: 8 row-groups(8)
    int brow = blockIdx.x * 64;
    int bcol = blockIdx.y * 64;
    float acc[8][4];
    #pragma unroll
    for (int i = 0; i < 8; i++)
        #pragma unroll
        for (int j = 0; j < 4; j++) acc[i][j] = 0.f;

    for (int kt = 0; kt < 4; kt++) {
        #pragma unroll
        for (int r = 0; r < 16; r++) {
            int lin = tid + 128 * r;
            int m = lin >> 5, k = lin & 31;
            int gm = brow + m;
            As[k][m] = (gm < M) ? A[gm * 128 + kt * 32 + k] : 0.f;
        }
        #pragma unroll
        for (int r = 0; r < 16; r++) {
            int lin = tid + 128 * r;
            int k = lin >> 6, n = lin & 63;
            Bs[k][n] = B[(kt * 32 + k) * N + bcol + n];
        }
        __syncthreads();
        #pragma unroll
        for (int k = 0; k < 32; k++) {
            float4 a0 = *reinterpret_cast<const float4*>(&As[k][ty * 8]);
            float4 a1 = *reinterpret_cast<const float4*>(&As[k][ty * 8 + 4]);
            float4 b  = *reinterpret_cast<const float4*>(&Bs[k][tx * 4]);
            float av[8] = {a0.x, a0.y, a0.z, a0.w, a1.x, a1.y, a1.z, a1.w};
            float bv[4] = {b.x, b.y, b.z, b.w};
            #pragma unroll
            for (int i = 0; i < 8; i++)
                #pragma unroll
                for (int j = 0; j < 4; j++)
                    acc[i][j] += av[i] * bv[j];
        }
        __syncthreads();
    }
    float bv[4];
    #pragma unroll
    for (int j = 0; j < 4; j++) bv[j] = bias[bcol + tx * 4 + j];
    #pragma unroll
    for (int i = 0; i < 8; i++) {
        int row = brow + ty * 8 + i;
        if (row < M) {
            float o[4];
            #pragma unroll
            for (int j = 0; j < 4; j++) {
                float c = acc[i][j] + bv[j];
                if (ACT) c = c / (1.0f + expf(-c));   // silu
                o[j] = c;
            }
            *reinterpret_cast<float4*>(&C[row * N + bcol + tx * 4]) =
                make_float4(o[0], o[1], o[2], o[3]);
        }
    }
}

// ---------------- edge kernel: scatter with v4 reductions, SoA v ----------
template<bool FIRST>
__global__ void __launch_bounds__(128)
edge_kernel(const float* __restrict__ phi, const float* __restrict__ v_in,
            float* __restrict__ s_acc, float* __restrict__ v_acc,
            const float* __restrict__ Wr, const float* __restrict__ brv) {
    __shared__ float rbf_s[16 * 20];
    __shared__ float ux_s[16], uy_s[16], uz_s[16];
    __shared__ float env_s[16];
    __shared__ int   ii_s[16];
    __shared__ int   jj_s[16];
    __shared__ float prod_s[16 * 512];   // SoA per edge: [s(128)|vx|vy|vz]
    int t = threadIdx.x;

    // Wr columns for features {t, 128+t, 256+t} live in registers
    float wr[60];
    #pragma unroll
    for (int k = 0; k < 20; k++) {
        wr[k]      = Wr[k * 384 + t];
        wr[20 + k] = Wr[k * 384 + 128 + t];
        wr[40 + k] = Wr[k * 384 + 256 + t];
    }
    float br0 = brv[t], br1 = brv[128 + t], br2 = brv[256 + t];

    int count = g_count;
    int ntiles = (count + 15) >> 4;
    for (int tile = blockIdx.x; tile < ntiles; tile += gridDim.x) {
        int e0 = tile << 4;
        int emax = min(16, count - e0);
        if (t < 16 && t < emax) {
            ii_s[t]  = g_ei[e0 + t];
            jj_s[t]  = g_ej[e0 + t];
            env_s[t] = g_env[e0 + t];
            ux_s[t]  = g_ux[e0 + t];
            uy_s[t]  = g_uy[e0 + t];
            uz_s[t]  = g_uz[e0 + t];
        }
        for (int x = t; x < 320; x += 128)
            if ((x / 20) < emax) rbf_s[x] = g_rbf[e0 * 20 + x];
        __syncthreads();

        for (int e = 0; e < emax; e++) {
            int j = jj_s[e];
            float ws0 = br0, ws1 = br1, ws2 = br2;
            #pragma unroll
            for (int k = 0; k < 20; k++) {
                float rv = rbf_s[e * 20 + k];
                ws0 += rv * wr[k];
                ws1 += rv * wr[20 + k];
                ws2 += rv * wr[40 + k];
            }
            float env = env_s[e];
            const float* pj = phi + (size_t)j * 384;
            float ds = pj[t]       * ws0 * env;
            float gv = pj[128 + t] * ws1 * env;
            float gu = pj[256 + t] * ws2 * env;
            float ax, ay, az;
            if (FIRST) {
                ax = gu * ux_s[e]; ay = gu * uy_s[e]; az = gu * uz_s[e];
            } else {
                const float* vj = v_in + (size_t)j * 384;
                ax = gu * ux_s[e] + gv * vj[t];
                ay = gu * uy_s[e] + gv * vj[128 + t];
                az = gu * uz_s[e] + gv * vj[256 + t];
            }
            prod_s[e * 512 + t]       = ds;
            prod_s[e * 512 + 128 + t] = ax;
            prod_s[e * 512 + 256 + t] = ay;
            prod_s[e * 512 + 384 + t] = az;
        }
        __syncthreads();

        for (int e = 0; e < emax; e++) {
            int node = ii_s[e];
            const float4 val = *reinterpret_cast<const float4*>(&prod_s[e * 512 + t * 4]);
            float* dst = (t < 32) ? (s_acc + node * 128 + t * 4)
                                  : (v_acc + node * 384 + (t - 32) * 4);
            red4(dst, val.x, val.y, val.z, val.w);
        }
        __syncthreads();
    }
}

// ---------------- epilogue: SoA v -> interleaved (N,128,3) ----------------
__global__ void __launch_bounds__(128)
interleave_kernel(const float* __restrict__ v_soa, float* __restrict__ out) {
    __shared__ float sm[384];
    int i = blockIdx.x;
    int t = threadIdx.x;
    sm[t]       = v_soa[i * 384 + t];
    sm[128 + t] = v_soa[i * 384 + 128 + t];
    sm[256 + t] = v_soa[i * 384 + 256 + t];
    __syncthreads();
    #pragma unroll
    for (int r = 0; r < 3; r++) {
        int x = t + 128 * r;
        out[i * 384 + x] = sm[(x % 3) * 128 + x / 3];
    }
}

// ---------------- orchestration -------------------------------------------
extern "C" void kernel_launch(void* const* d_in, const int* in_sizes, int n_in,
                              void* d_out, int out_size) {
    (void)in_sizes; (void)n_in; (void)out_size;
    const float* xyz  = (const float*)d_in[0];
    const int*   nbr  = (const int*)d_in[1];
    const float* cg_s = (const float*)d_in[2];
    const float* W1   = (const float*)d_in[3];
    const float* b1   = (const float*)d_in[4];
    const float* W2   = (const float*)d_in[5];
    const float* b2   = (const float*)d_in[6];
    const float* Wr   = (const float*)d_in[7];
    const float* brr  = (const float*)d_in[8];
    float* s_out = (float*)d_out;                       // (N,128)
    float* v_out_final = s_out + (size_t)NN * 128;      // (N,128,3)

    void *p_count, *p_h, *p_phi, *p_va, *p_vb;
    cudaGetSymbolAddress(&p_count, g_count);
    cudaGetSymbolAddress(&p_h, g_h);
    cudaGetSymbolAddress(&p_phi, g_phi);
    cudaGetSymbolAddress(&p_va, g_va);
    cudaGetSymbolAddress(&p_vb, g_vb);

    size_t vbytes = (size_t)NN * 384 * sizeof(float);
    cudaMemsetAsync(p_count, 0, sizeof(int));
    cudaMemsetAsync(p_va, 0, vbytes);
    cudaMemcpyAsync(s_out, cg_s, (size_t)NN * 128 * sizeof(float),
                    cudaMemcpyDeviceToDevice);

    precompute_kernel<<<(NE + 127) / 128, 128>>>(xyz, nbr);

    dim3 g1((NN + 63) / 64, 2), g2((NN + 63) / 64, 6);

    // layer 0: v_in unused (zero), scatter into va (zeroed)
    gemm64x64<1><<<g1, 128>>>(s_out, W1, b1, (float*)p_h, NN, 128);
    gemm64x64<0><<<g2, 128>>>((const float*)p_h, W2, b2, (float*)p_phi, NN, 384);
    edge_kernel<true><<<1480, 128>>>((const float*)p_phi, nullptr,
                                     s_out, (float*)p_va, Wr, brr);
    // layer 1: read va, scatter into vb (= copy of va)
    gemm64x64<1><<<g1, 128>>>(s_out, W1 + 128 * 128, b1 + 128, (float*)p_h, NN, 128);
    gemm64x64<0><<<g2, 128>>>((const float*)p_h, W2 + 128 * 384, b2 + 384,
                              (float*)p_phi, NN, 384);
    cudaMemcpyAsync(p_vb, p_va, vbytes, cudaMemcpyDeviceToDevice);
    edge_kernel<false><<<1480, 128>>>((const float*)p_phi, (const float*)p_va,
                                      s_out, (float*)p_vb,
                                      Wr + 20 * 384, brr + 384);
    // layer 2: read vb, scatter into va (= copy of vb)
    gemm64x64<1><<<g1, 128>>>(s_out, W1 + 2 * 128 * 128, b1 + 2 * 128,
                              (float*)p_h, NN, 128);
    gemm64x64<0><<<g2, 128>>>((const float*)p_h, W2 + 2 * 128 * 384, b2 + 2 * 384,
                              (float*)p_phi, NN, 384);
    cudaMemcpyAsync(p_va, p_vb, vbytes, cudaMemcpyDeviceToDevice);
    edge_kernel<false><<<1480, 128>>>((const float*)p_phi, (const float*)p_vb,
                                      s_out, (float*)p_va,
                                      Wr + 2 * 20 * 384, brr + 2 * 384);

    interleave_kernel<<<NN, 128>>>((const float*)p_va, v_out_final);
}

// round 4
// speedup vs baseline: 1.6035x; 1.0016x over previous
#include <cuda_runtime.h>
#include <math.h>

#define NN 10000
#define NE 160000

// ---------------- device scratch (no allocations allowed) ----------------
__device__ int   g_count;
__device__ int   g_ei[NE];
__device__ int   g_ej[NE];
__device__ float g_env[NE];
__device__ float g_ux[NE];
__device__ float g_uy[NE];
__device__ float g_uz[NE];
__device__ float g_rbf[NE * 20];
__device__ float g_h[NN * 128];
__device__ float g_phi[NN * 384];
__device__ float g_va[NN * 384];   // SoA: [node][coord][128]
__device__ float g_vb[NN * 384];   // SoA

__device__ __forceinline__ void red4(float* a, float x, float y, float z, float w) {
    asm volatile("red.global.add.v4.f32 [%0], {%1,%2,%3,%4};"
                 :: "l"(a), "f"(x), "f"(y), "f"(z), "f"(w) : "memory");
}

// ---------------- per-edge geometry + RBF precompute (with compaction) ----
__global__ void precompute_kernel(const float* __restrict__ xyz,
                                  const int* __restrict__ nbr) {
    int e = blockIdx.x * blockDim.x + threadIdx.x;
    bool active = false;
    int ni = 0, nj = 0;
    float rx = 0.f, ry = 0.f, rz = 0.f, dist = 1.f;
    if (e < NE) {
        ni = nbr[2 * e]; nj = nbr[2 * e + 1];
        float x0 = xyz[3 * ni], x1 = xyz[3 * ni + 1], x2 = xyz[3 * ni + 2];
        rx = xyz[3 * nj]     - x0;
        ry = xyz[3 * nj + 1] - x1;
        rz = xyz[3 * nj + 2] - x2;
        dist = sqrtf(rx * rx + ry * ry + rz * rz + 3e-15f);
        active = (dist < 5.0f);   // env==0 edges contribute nothing: drop them
    }
    unsigned mask = __ballot_sync(0xffffffffu, active);
    if (!active) return;
    int lane = threadIdx.x & 31;
    int rank = __popc(mask & ((1u << lane) - 1u));
    int leader = __ffs((int)mask) - 1;
    int base = 0;
    if (lane == leader) base = atomicAdd(&g_count, __popc(mask));
    base = __shfl_sync(mask, base, leader);
    int pos = base + rank;

    float inv = 1.0f / dist;
    g_ei[pos] = ni; g_ej[pos] = nj;
    g_ux[pos] = rx * inv;
    g_uy[pos] = ry * inv;
    g_uz[pos] = rz * inv;
    g_env[pos] = 0.5f * (cosf(dist * 0.6283185307179586f) + 1.0f);

    // rbf[k] = exp(-beta*(exp(-d)-mu_k)^2), mu_k linspace -> mult. recurrence
    const float MU0   = 0.006737946999085467f;   // exp(-5)
    const float DELTA = 0.05227695015794287f;    // (1-exp(-5))/19
    const float BETA  = 101.3613328f;            // (0.1*(1-exp(-5)))^-2
    float x  = expf(-dist);
    float u  = x - MU0;
    float a0 = expf(-BETA * u * u);
    float tt = expf(2.0f * BETA * DELTA * u);
    float s1 = expf(-BETA * DELTA * DELTA);
    float s2 = s1 * s1;
    float val = a0;
    float f = tt * s1;
    #pragma unroll
    for (int k = 0; k < 20; k++) {
        g_rbf[20 * pos + k] = val;
        val *= f;
        f *= s2;
    }
}

// ---------------- fp32 SGEMM 64x64 tiles, K=128: C = act(A@B + bias) ------
template<int ACT>
__global__ void __launch_bounds__(128)
gemm64x64(const float* __restrict__ A, const float* __restrict__ B,
          const float* __restrict__ bias, float* __restrict__ C,
          int M, int N) {
    __shared__ float As[32][68];
    __shared__ float Bs[32][68];
    int tid = threadIdx.x;
    int tx = tid & 15, ty = tid >> 4;       // tx: 16 col-groups(4), ty: 8 row-groups(8)
    int brow = blockIdx.x * 64;
    int bcol = blockIdx.y * 64;
    float acc[8][4];
    #pragma unroll
    for (int i = 0; i < 8; i++)
        #pragma unroll
        for (int j = 0; j < 4; j++) acc[i][j] = 0.f;

    for (int kt = 0; kt < 4; kt++) {
        #pragma unroll
        for (int r = 0; r < 16; r++) {
            int lin = tid + 128 * r;
            int m = lin >> 5, k = lin & 31;
            int gm = brow + m;
            As[k][m] = (gm < M) ? A[gm * 128 + kt * 32 + k] : 0.f;
        }
        #pragma unroll
        for (int r = 0; r < 16; r++) {
            int lin = tid + 128 * r;
            int k = lin >> 6, n = lin & 63;
            Bs[k][n] = B[(kt * 32 + k) * N + bcol + n];
        }
        __syncthreads();
        #pragma unroll
        for (int k = 0; k < 32; k++) {
            float4 a0 = *reinterpret_cast<const float4*>(&As[k][ty * 8]);
            float4 a1 = *reinterpret_cast<const float4*>(&As[k][ty * 8 + 4]);
            float4 b  = *reinterpret_cast<const float4*>(&Bs[k][tx * 4]);
            float av[8] = {a0.x, a0.y, a0.z, a0.w, a1.x, a1.y, a1.z, a1.w};
            float bv[4] = {b.x, b.y, b.z, b.w};
            #pragma unroll
            for (int i = 0; i < 8; i++)
                #pragma unroll
                for (int j = 0; j < 4; j++)
                    acc[i][j] += av[i] * bv[j];
        }
        __syncthreads();
    }
    float bv[4];
    #pragma unroll
    for (int j = 0; j < 4; j++) bv[j] = bias[bcol + tx * 4 + j];
    #pragma unroll
    for (int i = 0; i < 8; i++) {
        int row = brow + ty * 8 + i;
        if (row < M) {
            float o[4];
            #pragma unroll
            for (int j = 0; j < 4; j++) {
                float c = acc[i][j] + bv[j];
                if (ACT) c = c / (1.0f + expf(-c));   // silu
                o[j] = c;
            }
            *reinterpret_cast<float4*>(&C[row * N + bcol + tx * 4]) =
                make_float4(o[0], o[1], o[2], o[3]);
        }
    }
}

// ---------------- edge kernel: scatter with v4 reductions, SoA v ----------
template<bool FIRST>
__global__ void __launch_bounds__(128)
edge_kernel(const float* __restrict__ phi, const float* __restrict__ v_in,
            float* __restrict__ s_acc, float* __restrict__ v_acc,
            const float* __restrict__ Wr, const float* __restrict__ brv) {
    __shared__ float rbf_s[16 * 20];
    __shared__ float ux_s[16], uy_s[16], uz_s[16];
    __shared__ float env_s[16];
    __shared__ int   ii_s[16];
    __shared__ int   jj_s[16];
    __shared__ float prod_s[16 * 512];   // SoA per edge: [s(128)|vx|vy|vz]
    int t = threadIdx.x;

    // Wr columns for features {t, 128+t, 256+t} live in registers
    float wr[60];
    #pragma unroll
    for (int k = 0; k < 20; k++) {
        wr[k]      = Wr[k * 384 + t];
        wr[20 + k] = Wr[k * 384 + 128 + t];
        wr[40 + k] = Wr[k * 384 + 256 + t];
    }
    float br0 = brv[t], br1 = brv[128 + t], br2 = brv[256 + t];

    int count = g_count;
    int ntiles = (count + 15) >> 4;
    for (int tile = blockIdx.x; tile < ntiles; tile += gridDim.x) {
        int e0 = tile << 4;
        int emax = min(16, count - e0);
        if (t < 16 && t < emax) {
            ii_s[t]  = g_ei[e0 + t];
            jj_s[t]  = g_ej[e0 + t];
            env_s[t] = g_env[e0 + t];
            ux_s[t]  = g_ux[e0 + t];
            uy_s[t]  = g_uy[e0 + t];
            uz_s[t]  = g_uz[e0 + t];
        }
        for (int x = t; x < 320; x += 128)
            if ((x / 20) < emax) rbf_s[x] = g_rbf[e0 * 20 + x];
        __syncthreads();

        for (int e = 0; e < emax; e++) {
            int j = jj_s[e];
            float ws0 = br0, ws1 = br1, ws2 = br2;
            #pragma unroll
            for (int k = 0; k < 20; k++) {
                float rv = rbf_s[e * 20 + k];
                ws0 += rv * wr[k];
                ws1 += rv * wr[20 + k];
                ws2 += rv * wr[40 + k];
            }
            float env = env_s[e];
            const float* pj = phi + (size_t)j * 384;
            float ds = pj[t]       * ws0 * env;
            float gv = pj[128 + t] * ws1 * env;
            float gu = pj[256 + t] * ws2 * env;
            float ax, ay, az;
            if (FIRST) {
                ax = gu * ux_s[e]; ay = gu * uy_s[e]; az = gu * uz_s[e];
            } else {
                const float* vj = v_in + (size_t)j * 384;
                ax = gu * ux_s[e] + gv * vj[t];
                ay = gu * uy_s[e] + gv * vj[128 + t];
                az = gu * uz_s[e] + gv * vj[256 + t];
            }
            prod_s[e * 512 + t]       = ds;
            prod_s[e * 512 + 128 + t] = ax;
            prod_s[e * 512 + 256 + t] = ay;
            prod_s[e * 512 + 384 + t] = az;
        }
        __syncthreads();

        for (int e = 0; e < emax; e++) {
            int node = ii_s[e];
            const float4 val = *reinterpret_cast<const float4*>(&prod_s[e * 512 + t * 4]);
            float* dst = (t < 32) ? (s_acc + node * 128 + t * 4)
                                  : (v_acc + node * 384 + (t - 32) * 4);
            red4(dst, val.x, val.y, val.z, val.w);
        }
        __syncthreads();
    }
}

// ---------------- epilogue: SoA v -> interleaved (N,128,3) ----------------
__global__ void __launch_bounds__(128)
interleave_kernel(const float* __restrict__ v_soa, float* __restrict__ out) {
    __shared__ float sm[384];
    int i = blockIdx.x;
    int t = threadIdx.x;
    sm[t]       = v_soa[i * 384 + t];
    sm[128 + t] = v_soa[i * 384 + 128 + t];
    sm[256 + t] = v_soa[i * 384 + 256 + t];
    __syncthreads();
    #pragma unroll
    for (int r = 0; r < 3; r++) {
        int x = t + 128 * r;
        out[i * 384 + x] = sm[(x % 3) * 128 + x / 3];
    }
}

// ---------------- orchestration -------------------------------------------
extern "C" void kernel_launch(void* const* d_in, const int* in_sizes, int n_in,
                              void* d_out, int out_size) {
    (void)in_sizes; (void)n_in; (void)out_size;
    const float* xyz  = (const float*)d_in[0];
    const int*   nbr  = (const int*)d_in[1];
    const float* cg_s = (const float*)d_in[2];
    const float* W1   = (const float*)d_in[3];
    const float* b1   = (const float*)d_in[4];
    const float* W2   = (const float*)d_in[5];
    const float* b2   = (const float*)d_in[6];
    const float* Wr   = (const float*)d_in[7];
    const float* brr  = (const float*)d_in[8];
    float* s_out = (float*)d_out;                       // (N,128)
    float* v_out_final = s_out + (size_t)NN * 128;      // (N,128,3)

    void *p_count, *p_h, *p_phi, *p_va, *p_vb;
    cudaGetSymbolAddress(&p_count, g_count);
    cudaGetSymbolAddress(&p_h, g_h);
    cudaGetSymbolAddress(&p_phi, g_phi);
    cudaGetSymbolAddress(&p_va, g_va);
    cudaGetSymbolAddress(&p_vb, g_vb);

    size_t vbytes = (size_t)NN * 384 * sizeof(float);
    cudaMemsetAsync(p_count, 0, sizeof(int));
    cudaMemsetAsync(p_va, 0, vbytes);
    cudaMemcpyAsync(s_out, cg_s, (size_t)NN * 128 * sizeof(float),
                    cudaMemcpyDeviceToDevice);

    precompute_kernel<<<(NE + 127) / 128, 128>>>(xyz, nbr);

    dim3 g1((NN + 63) / 64, 2), g2((NN + 63) / 64, 6);

    // layer 0: v_in unused (zero), scatter into va (zeroed)
    gemm64x64<1><<<g1, 128>>>(s_out, W1, b1, (float*)p_h, NN, 128);
    gemm64x64<0><<<g2, 128>>>((const float*)p_h, W2, b2, (float*)p_phi, NN, 384);
    edge_kernel<true><<<1480, 128>>>((const float*)p_phi, nullptr,
                                     s_out, (float*)p_va, Wr, brr);
    // layer 1: read va, scatter into vb (= copy of va)
    gemm64x64<1><<<g1, 128>>>(s_out, W1 + 128 * 128, b1 + 128, (float*)p_h, NN, 128);
    gemm64x64<0><<<g2, 128>>>((const float*)p_h, W2 + 128 * 384, b2 + 384,
                              (float*)p_phi, NN, 384);
    cudaMemcpyAsync(p_vb, p_va, vbytes, cudaMemcpyDeviceToDevice);
    edge_kernel<false><<<1480, 128>>>((const float*)p_phi, (const float*)p_va,
                                      s_out, (float*)p_vb,
                                      Wr + 20 * 384, brr + 384);
    // layer 2: read vb, scatter into va (= copy of vb)
    gemm64x64<1><<<g1, 128>>>(s_out, W1 + 2 * 128 * 128, b1 + 2 * 128,
                              (float*)p_h, NN, 128);
    gemm64x64<0><<<g2, 128>>>((const float*)p_h, W2 + 2 * 128 * 384, b2 + 2 * 384,
                              (float*)p_phi, NN, 384);
    cudaMemcpyAsync(p_va, p_vb, vbytes, cudaMemcpyDeviceToDevice);
    edge_kernel<false><<<1480, 128>>>((const float*)p_phi, (const float*)p_vb,
                                      s_out, (float*)p_va,
                                      Wr + 2 * 20 * 384, brr + 2 * 384);

    interleave_kernel<<<NN, 128>>>((const float*)p_va, v_out_final);
}